// round 11
// baseline (speedup 1.0000x reference)
#include <cuda_runtime.h>

#define CH 4
#define HDIM 1025
#define WDIM 1024
#define NTOT (CH*HDIM*WDIM)
#define STRIDE_T 1028
#define NT_T (CH*WDIM*STRIDE_T)
#define SEG 64
#define BS 128

// colmed grid constants
#define NJOBS_H (16 * CH * HDIM)            /* 16 segs * 4 ch * 1025 cols = 65600 */
#define BLOCKS_H ((NJOBS_H + BS - 1) / BS)  /* 513 */
#define NJOBS_P (17 * CH * WDIM)            /* 17 segs * 4 ch * 1024 cols = 69632 */
#define BLOCKS_P ((NJOBS_P + BS - 1) / BS)  /* 544 */

// scratch (allocation-free rule: __device__ globals)
__device__ __align__(16) float g_ST[NT_T];      // S transposed: (4, 1024, STRIDE_T), cols 0..1024 valid
__device__ __align__(16) float g_harmT[NT_T];   // harmonic median, transposed+padded layout
__device__ __align__(16) float g_perc[NTOT];    // percussive median, natural layout

__device__ __forceinline__ float finf() { return __int_as_float(0x7f800000); }

__device__ __forceinline__ void cas(float& a, float& b) {
    float lo = fminf(a, b);
    float hi = fmaxf(a, b);
    a = lo; b = hi;
}

// Batcher odd-even mergesort, n=32, fully unrolled -> registers
__device__ __forceinline__ void sort32(float* a) {
#pragma unroll
    for (int p = 1; p < 32; p <<= 1)
#pragma unroll
        for (int k = p; k >= 1; k >>= 1)
#pragma unroll
            for (int j = k & (p - 1); j + k < 32; j += 2 * k)
#pragma unroll
                for (int i = 0; i < k; ++i)
                    if (i + j + k < 32)
                        if (((i + j) / (2 * p)) == ((i + j + k) / (2 * p)))
                            cas(a[i + j], a[i + j + k]);
}

// ---------------- transpose v2: S (4,1025,1024) -> ST (4,1024,STRIDE_T) ----------------
__global__ void __launch_bounds__(256) transpose_kernel(const float* __restrict__ S) {
    __shared__ float tile[64 * 65];          // [w_local][h_local], stride 65
    int ch = blockIdx.z;
    int h0 = blockIdx.y * 64;
    int w0 = blockIdx.x * 64;
    int t = threadIdx.x;
    int fc = t & 15;                          // float4 column 0..15
    int rr = t >> 4;                          // 0..15
    const float* Sp = S + (size_t)ch * HDIM * WDIM;

#pragma unroll
    for (int k = 0; k < 4; ++k) {
        int r = rr + 16 * k;                  // h_local 0..63
        int h = h0 + r;
        float4 v = make_float4(0.f, 0.f, 0.f, 0.f);
        if (h < HDIM) v = *(const float4*)(Sp + (size_t)h * WDIM + w0 + 4 * fc);
        tile[(4 * fc + 0) * 65 + r] = v.x;
        tile[(4 * fc + 1) * 65 + r] = v.y;
        tile[(4 * fc + 2) * 65 + r] = v.z;
        tile[(4 * fc + 3) * 65 + r] = v.w;
    }
    __syncthreads();

    float* STp = g_ST + (size_t)ch * WDIM * STRIDE_T;
    if (h0 + 4 * fc <= 1024) {                // keep all writes inside each padded row
#pragma unroll
        for (int k = 0; k < 4; ++k) {
            int wr = rr + 16 * k;             // w_local
            float4 o;
            o.x = tile[wr * 65 + 4 * fc + 0];
            o.y = tile[wr * 65 + 4 * fc + 1];
            o.z = tile[wr * 65 + 4 * fc + 2];
            o.w = tile[wr * 65 + 4 * fc + 3];
            *(float4*)(STp + (size_t)(w0 + wr) * STRIDE_T + h0 + 4 * fc) = o;
        }
    }
}

// ---------------- sliding sorted-window median-31 over one column segment --------------
template<int R, int STRIDE>
__device__ __forceinline__ void colmed_run(const float* __restrict__ in,
                                           float* __restrict__ out,
                                           int r0, int r1) {
    float v[32];
#pragma unroll
    for (int i = 0; i < 31; ++i) {
        int p = r0 - 15 + i;
        float x = 0.f;
        if (p >= 0 && p < R) x = in[(size_t)p * STRIDE];
        v[i] = x;
    }
    v[31] = finf();
    sort32(v);

    float xo = (r0 >= 15) ? in[(size_t)(r0 - 15) * STRIDE] : 0.f;
    float xi = (r0 + 16 < R) ? in[(size_t)(r0 + 16) * STRIDE] : 0.f;

#pragma unroll 2
    for (int r = r0; r < r1; ++r) {
        out[(size_t)r * STRIDE] = v[15];
        float cxo = xo, cxi = xi;
        int ro = r - 14, ri = r + 17;
        xo = (ro >= 0) ? in[(size_t)ro * STRIDE] : 0.f;
        xi = (ri < R) ? in[(size_t)ri * STRIDE] : 0.f;

        // branch-free parallel replace: d[i] = (v[i]<cxo ? v[i] : v[i+1]);
        // new[i] = min(max(d[i-1], cxi), d[i])
        float dc = (v[30] < cxo) ? v[30] : finf();
#pragma unroll
        for (int i = 30; i >= 1; --i) {
            float dp = (v[i - 1] < cxo) ? v[i - 1] : v[i];
            v[i] = fminf(fmaxf(dp, cxi), dc);
            dc = dp;
        }
        v[0] = fminf(cxi, dc);
    }
}

// ---------------- split colmed kernels (identical inner code) ------------
__global__ void __launch_bounds__(BS, 6) colmed_h_kernel() {
    int job = blockIdx.x * BS + threadIdx.x;
    if (job >= NJOBS_H) return;
    const int nCols = CH * HDIM;
    int seg = job / nCols;
    int rem = job - seg * nCols;
    int ch = rem / HDIM;
    int c = rem - ch * HDIM;
    const float* in = g_ST + (size_t)ch * WDIM * STRIDE_T + c;
    float* out = g_harmT + (size_t)ch * WDIM * STRIDE_T + c;
    int r0 = seg * SEG;
    colmed_run<WDIM, STRIDE_T>(in, out, r0, min(r0 + SEG, WDIM));
}

__global__ void __launch_bounds__(BS, 6) colmed_p_kernel(const float* __restrict__ S) {
    int job = blockIdx.x * BS + threadIdx.x;
    if (job >= NJOBS_P) return;
    const int nCols = CH * WDIM;
    int seg = job / nCols;
    int rem = job - seg * nCols;
    int ch = rem / WDIM;
    int c = rem - ch * WDIM;
    const float* in = S + (size_t)ch * HDIM * WDIM + c;
    float* out = g_perc + (size_t)ch * HDIM * WDIM + c;
    int r0 = seg * SEG;
    colmed_run<HDIM, WDIM>(in, out, r0, min(r0 + SEG, HDIM));
}

// ---------------- mask v2: 32h x 128w tile, float4 gmem, smem de-transpose -------------
__global__ void __launch_bounds__(256) mask_kernel(const float4* __restrict__ S4,
                                                   float4* __restrict__ outA,
                                                   float4* __restrict__ outB) {
    __shared__ float tile[128][33];           // [w_local][h_local]
    int ch = blockIdx.z;
    int h0 = blockIdx.y * 32;
    int w0 = blockIdx.x * 128;
    int tx = threadIdx.x, ty = threadIdx.y;   // (32, 8)

    const float* HT = g_harmT + (size_t)ch * WDIM * STRIDE_T;
    int hcl = min(h0 + tx, STRIDE_T - 1);
#pragma unroll
    for (int wi = 0; wi < 16; ++wi) {
        int wl = ty + 8 * wi;
        tile[wl][tx] = HT[(size_t)(w0 + wl) * STRIDE_T + hcl];
    }
    __syncthreads();

    const float4* P4 = (const float4*)g_perc;
    size_t chOff4 = (size_t)ch * HDIM * (WDIM / 4);
#pragma unroll
    for (int p = 0; p < 4; ++p) {
        int hl = ty + 8 * p;
        int h = h0 + hl;
        if (h < HDIM) {
            size_t idx4 = chOff4 + (size_t)h * (WDIM / 4) + (w0 >> 2) + tx;
            float4 s = S4[idx4];
            float4 pv = P4[idx4];
            float hv0 = tile[4 * tx + 0][hl];
            float hv1 = tile[4 * tx + 1][hl];
            float hv2 = tile[4 * tx + 2][hl];
            float hv3 = tile[4 * tx + 3][hl];
            float4 oa, ob;
            {
                float hh = hv0 * hv0, pp = pv.x * pv.x;
                float rcp = __fdividef(1.0f, fmaxf(hh + pp, 1e-30f));
                oa.x = s.x * hh * rcp; ob.x = s.x * pp * rcp;
            }
            {
                float hh = hv1 * hv1, pp = pv.y * pv.y;
                float rcp = __fdividef(1.0f, fmaxf(hh + pp, 1e-30f));
                oa.y = s.y * hh * rcp; ob.y = s.y * pp * rcp;
            }
            {
                float hh = hv2 * hv2, pp = pv.z * pv.z;
                float rcp = __fdividef(1.0f, fmaxf(hh + pp, 1e-30f));
                oa.z = s.z * hh * rcp; ob.z = s.z * pp * rcp;
            }
            {
                float hh = hv3 * hv3, pp = pv.w * pv.w;
                float rcp = __fdividef(1.0f, fmaxf(hh + pp, 1e-30f));
                oa.w = s.w * hh * rcp; ob.w = s.w * pp * rcp;
            }
            outA[idx4] = oa;
            outB[idx4] = ob;
        }
    }
}

extern "C" void kernel_launch(void* const* d_in, const int* in_sizes, int n_in,
                              void* d_out, int out_size) {
    const float* S = (const float*)d_in[0];
    float* out = (float*)d_out;

    // one-time resource init (streams/events are resources, not work; every call
    // issues the identical kernel DAG). Created outside any capture path's graph.
    static cudaStream_t s1 = nullptr;
    static cudaEvent_t eFork = nullptr, eJoin = nullptr;
    if (s1 == nullptr) {
        cudaStreamCreateWithFlags(&s1, cudaStreamNonBlocking);
        cudaEventCreateWithFlags(&eFork, cudaEventDisableTiming);
        cudaEventCreateWithFlags(&eJoin, cudaEventDisableTiming);
    }

    // fork: base stream (0) -> s1
    cudaEventRecord(eFork, 0);
    cudaStreamWaitEvent(s1, eFork, 0);

    // s1 branch: transpose then harmonic medians (depends on transpose only)
    transpose_kernel<<<dim3(WDIM / 64, (HDIM + 63) / 64, CH), 256, 0, s1>>>(S);
    colmed_h_kernel<<<BLOCKS_H, BS, 0, s1>>>();
    cudaEventRecord(eJoin, s1);

    // base branch: percussive medians (independent of transpose), runs concurrently
    colmed_p_kernel<<<BLOCKS_P, BS>>>(S);

    // join, then masks + both outputs
    cudaStreamWaitEvent(0, eJoin, 0);
    mask_kernel<<<dim3(WDIM / 128, (HDIM + 31) / 32, CH), dim3(32, 8)>>>(
        (const float4*)S, (float4*)out, (float4*)(out + NTOT));
}